// round 1
// baseline (speedup 1.0000x reference)
#include <cuda_runtime.h>
#include <cuda_bf16.h>
#include <math.h>

// ---------------------------------------------------------------------------
// DGCNN forward.  B=8, N=1024, KNN=20.
// Stage features stored n-major: X[b][n][c] (row-major per batch).
// edge_conv(x, w):  y[o,n,k] = wd@x[idx] + (wc-wd)@x[n] (+bias);  bn,lrelu,max_k
// ---------------------------------------------------------------------------

#define BB   8
#define NN   1024
#define KNN  20

// ------------------------- scratch (device globals) ------------------------
__device__ float g_inner[BB * NN * NN];     // 32MB: Gram matrices / conv5 out
__device__ float g_xx[BB * NN];
__device__ int   g_idx[BB * NN * KNN];
__device__ float g_A[BB * NN * 256];        // wd @ x   (n-major)
__device__ float g_Bc[BB * NN * 256];       // (wc-wd) @ x
__device__ float g_X1[BB * NN * 64];
__device__ float g_X2[BB * NN * 64];
__device__ float g_X3[BB * NN * 128];
__device__ float g_X4[BB * NN * 256];
__device__ float g_Xc[BB * NN * 512];       // concat
__device__ float g_wd[256 * 128];
__device__ float g_wcd[256 * 128];
__device__ float g_gpool[BB * NN];

// --------------------------- row squared norms ------------------------------
__global__ void rownorm_kernel(const float* __restrict__ X, float* __restrict__ xx, int C)
{
    int i = blockIdx.x * blockDim.x + threadIdx.x;   // over B*N
    if (i < BB * NN) {
        const float* r = X + (long)i * C;
        float s = 0.f;
        for (int c = 0; c < C; c++) s += r[c] * r[c];
        xx[i] = s;
    }
}

// --------------------------- weight split -----------------------------------
// w: (O, 2C) row-major.  wd = w[:, :C];  wcd = w[:, C:] - w[:, :C]
__global__ void wsplit_kernel(const float* __restrict__ w,
                              float* __restrict__ wd, float* __restrict__ wcd,
                              int O, int C)
{
    int i = blockIdx.x * blockDim.x + threadIdx.x;
    if (i < O * C) {
        int o = i / C, c = i % C;
        float a = w[(long)o * 2 * C + c];
        float b = w[(long)o * 2 * C + C + c];
        wd[i]  = a;
        wcd[i] = b - a;
    }
}

// --------------------------- tiled GEMM (NT) --------------------------------
// C[m][n] = sum_k A[m][k] * Bm[n][k],  per-batch strides (blockIdx.z = batch)
// BM=BN=64, BK=16, 256 threads, 4x4 register tile.
#define TBM 64
#define TBN 64
#define TBK 16
__global__ void gemm_nt(const float* __restrict__ A, const float* __restrict__ Bm,
                        float* __restrict__ C, int M, int N, int K,
                        long sA, long sB, long sC)
{
    int bz = blockIdx.z;
    A  += (long)bz * sA;
    Bm += (long)bz * sB;
    C  += (long)bz * sC;

    int m0 = blockIdx.x * TBM;
    int n0 = blockIdx.y * TBN;

    __shared__ float As[TBK][TBM];
    __shared__ float Bs[TBK][TBN];

    int tid = threadIdx.x;
    int ty = tid / 16, tx = tid % 16;

    float acc[4][4];
#pragma unroll
    for (int i = 0; i < 4; i++)
#pragma unroll
        for (int j = 0; j < 4; j++) acc[i][j] = 0.f;

    for (int k0 = 0; k0 < K; k0 += TBK) {
#pragma unroll
        for (int l0 = 0; l0 < (TBM * TBK) / 256; l0++) {
            int l = tid + l0 * 256;
            int r = l / TBK, c = l % TBK;
            int ki = k0 + c;
            As[c][r] = (ki < K) ? A[(long)(m0 + r) * K + ki] : 0.f;
        }
#pragma unroll
        for (int l0 = 0; l0 < (TBN * TBK) / 256; l0++) {
            int l = tid + l0 * 256;
            int r = l / TBK, c = l % TBK;
            int ki = k0 + c;
            Bs[c][r] = (ki < K) ? Bm[(long)(n0 + r) * K + ki] : 0.f;
        }
        __syncthreads();

#pragma unroll
        for (int kk = 0; kk < TBK; kk++) {
            float a[4], bv[4];
#pragma unroll
            for (int i = 0; i < 4; i++) a[i] = As[kk][ty * 4 + i];
#pragma unroll
            for (int j = 0; j < 4; j++) bv[j] = Bs[kk][tx * 4 + j];
#pragma unroll
            for (int i = 0; i < 4; i++)
#pragma unroll
                for (int j = 0; j < 4; j++) acc[i][j] += a[i] * bv[j];
        }
        __syncthreads();
    }

#pragma unroll
    for (int i = 0; i < 4; i++) {
        long mi = m0 + ty * 4 + i;
#pragma unroll
        for (int j = 0; j < 4; j++)
            C[mi * N + n0 + tx * 4 + j] = acc[i][j];
    }
}

// --------------------------- top-k (k=20) ------------------------------------
// dist[m] = 2*inner[n][m] - xx[n] - xx[m];  iterative argmax, tie -> lower idx
__global__ void topk_kernel(const float* __restrict__ inner,
                            const float* __restrict__ xx,
                            int* __restrict__ idx)
{
    int n = blockIdx.x, b = blockIdx.y;
    __shared__ float d[NN];
    __shared__ float swv[8];
    __shared__ int   swi[8];

    int tid = threadIdx.x;
    float xn = xx[b * NN + n];
    const float* row = inner + ((long)b * NN + n) * NN;
    for (int m = tid; m < NN; m += 256)
        d[m] = 2.f * row[m] - xn - xx[b * NN + m];
    __syncthreads();

    int lane = tid & 31, warp = tid >> 5;
    for (int it = 0; it < KNN; it++) {
        float bv = -INFINITY;
        int   bi = 0x7fffffff;
        for (int m = tid; m < NN; m += 256) {
            float v = d[m];
            if (v > bv) { bv = v; bi = m; }   // increasing m: first occurrence kept
        }
#pragma unroll
        for (int off = 16; off > 0; off >>= 1) {
            float ov = __shfl_down_sync(0xffffffff, bv, off);
            int   oi = __shfl_down_sync(0xffffffff, bi, off);
            if (ov > bv || (ov == bv && oi < bi)) { bv = ov; bi = oi; }
        }
        if (lane == 0) { swv[warp] = bv; swi[warp] = bi; }
        __syncthreads();
        if (tid == 0) {
            float fv = swv[0];
            int   fi = swi[0];
            for (int w = 1; w < 8; w++)
                if (swv[w] > fv || (swv[w] == fv && swi[w] < fi)) { fv = swv[w]; fi = swi[w]; }
            idx[((long)b * NN + n) * KNN + it] = fi;
            d[fi] = -INFINITY;
        }
        __syncthreads();
    }
}

// --------------------------- gather + bn + lrelu + max ------------------------
__global__ void gathermax_kernel(const float* __restrict__ A,
                                 const float* __restrict__ Bc,
                                 const int* __restrict__ idx,
                                 const float* __restrict__ bias,
                                 const float* __restrict__ gg,
                                 const float* __restrict__ bb,
                                 float* __restrict__ Xout, int O)
{
    int n = blockIdx.x, b = blockIdx.y;
    __shared__ int nb[KNN];
    if (threadIdx.x < KNN)
        nb[threadIdx.x] = idx[((long)b * NN + n) * KNN + threadIdx.x];
    __syncthreads();

    const float rs = rsqrtf(1.f + 1e-5f);
    for (int o = threadIdx.x; o < O; o += blockDim.x) {
        float base = Bc[((long)b * NN + n) * O + o] + (bias ? bias[o] : 0.f);
        float gs = gg[o] * rs;
        float bo = bb[o];
        float acc = -INFINITY;
#pragma unroll
        for (int k = 0; k < KNN; k++) {
            float a = A[((long)b * NN + nb[k]) * O + o];
            float v = (a + base) * gs + bo;
            v = (v >= 0.f) ? v : 0.01f * v;
            acc = fmaxf(acc, v);
        }
        Xout[((long)b * NN + n) * O + o] = acc;
    }
}

// --------------------------- concat [x1,x2,x3,x4] ----------------------------
__global__ void concat_kernel(const float* __restrict__ X1, const float* __restrict__ X2,
                              const float* __restrict__ X3, const float* __restrict__ X4,
                              float* __restrict__ Xc)
{
    int n = blockIdx.x, b = blockIdx.y;
    long base = (long)b * NN + n;
    float* dst = Xc + base * 512;
    for (int c = threadIdx.x; c < 512; c += 256) {
        float v;
        if      (c < 64)  v = X1[base * 64  + c];
        else if (c < 128) v = X2[base * 64  + (c - 64)];
        else if (c < 256) v = X3[base * 128 + (c - 128)];
        else              v = X4[base * 256 + (c - 256)];
        dst[c] = v;
    }
}

// --------------------------- column max over n --------------------------------
// e: [b][n][1024] -> gpool[b][o] = max_n e[b][n][o]
__global__ void maxcol_kernel(const float* __restrict__ e, float* __restrict__ gpool)
{
    int b = blockIdx.y;
    int o = blockIdx.x * 256 + threadIdx.x;
    float m = -INFINITY;
    const float* eb = e + (long)b * NN * NN;
    for (int n = 0; n < NN; n++)
        m = fmaxf(m, eb[(long)n * NN + o]);
    gpool[b * NN + o] = m;
}

// --------------------------- MLP head -----------------------------------------
__global__ void mlp_head_kernel(const float* __restrict__ gpool,
                                const float* __restrict__ w1,
                                const float* __restrict__ g6, const float* __restrict__ b6,
                                const float* __restrict__ w2, const float* __restrict__ b2v,
                                const float* __restrict__ g7, const float* __restrict__ b7,
                                const float* __restrict__ w3, const float* __restrict__ b3v,
                                float* __restrict__ out)
{
    int b = blockIdx.x;
    int t = threadIdx.x;    // 512 threads
    __shared__ float s0[1024];
    __shared__ float s1[512];
    __shared__ float s2[256];

    for (int i = t; i < 1024; i += 512) s0[i] = gpool[b * 1024 + i];
    __syncthreads();

    const float rs = rsqrtf(1.f + 1e-5f);
    {
        const float* wr = w1 + (long)t * 1024;
        float acc = 0.f;
        for (int k = 0; k < 1024; k++) acc += s0[k] * wr[k];
        acc = acc * (g6[t] * rs) + b6[t];
        s1[t] = (acc >= 0.f) ? acc : 0.01f * acc;
    }
    __syncthreads();

    if (t < 256) {
        const float* wr = w2 + (long)t * 512;
        float acc = 0.f;
        for (int k = 0; k < 512; k++) acc += s1[k] * wr[k];
        acc += b2v[t];
        acc = acc * (g7[t] * rs) + b7[t];
        s2[t] = (acc >= 0.f) ? acc : 0.01f * acc;
    }
    __syncthreads();

    if (t < 40) {
        const float* wr = w3 + (long)t * 256;
        float acc = 0.f;
        for (int k = 0; k < 256; k++) acc += s2[k] * wr[k];
        out[b * 40 + t] = acc + b3v[t];
    }
}

// ---------------------------------------------------------------------------
// host side
// ---------------------------------------------------------------------------
static void run_edge_stage(const float* X, int C, int O,
                           const float* w, const float* bias,
                           const float* gg, const float* bbv,
                           float* Xout,
                           float* inner, float* xxp, int* idxp,
                           float* wd, float* wcd, float* Ap, float* Bp)
{
    rownorm_kernel<<<(BB * NN + 255) / 256, 256>>>(X, xxp, C);

    dim3 gi(NN / TBM, NN / TBN, BB);
    gemm_nt<<<gi, 256>>>(X, X, inner, NN, NN, C,
                         (long)NN * C, (long)NN * C, (long)NN * NN);

    topk_kernel<<<dim3(NN, BB), 256>>>(inner, xxp, idxp);

    wsplit_kernel<<<(O * C + 255) / 256, 256>>>(w, wd, wcd, O, C);

    dim3 ga(NN / TBM, O / TBN, BB);
    gemm_nt<<<ga, 256>>>(X, wd, Ap, NN, O, C, (long)NN * C, 0, (long)NN * O);
    gemm_nt<<<ga, 256>>>(X, wcd, Bp, NN, O, C, (long)NN * C, 0, (long)NN * O);

    gathermax_kernel<<<dim3(NN, BB), 128>>>(Ap, Bp, idxp, bias, gg, bbv, Xout, O);
}

extern "C" void kernel_launch(void* const* d_in, const int* in_sizes, int n_in,
                              void* d_out, int out_size)
{
    const float* x       = (const float*)d_in[0];    // (8,1024,3) n-major == stage-0 features
    const float* conv1_w = (const float*)d_in[1];
    const float* conv1_b = (const float*)d_in[2];
    const float* bn1_g   = (const float*)d_in[3];
    const float* bn1_b   = (const float*)d_in[4];
    const float* conv2_w = (const float*)d_in[5];
    const float* bn2_g   = (const float*)d_in[6];
    const float* bn2_b   = (const float*)d_in[7];
    const float* conv3_w = (const float*)d_in[8];
    const float* bn3_g   = (const float*)d_in[9];
    const float* bn3_b   = (const float*)d_in[10];
    const float* conv4_w = (const float*)d_in[11];
    const float* bn4_g   = (const float*)d_in[12];
    const float* bn4_b   = (const float*)d_in[13];
    const float* conv5_w = (const float*)d_in[14];
    const float* lin1_w  = (const float*)d_in[15];
    const float* bn6_g   = (const float*)d_in[16];
    const float* bn6_b   = (const float*)d_in[17];
    const float* lin2_w  = (const float*)d_in[18];
    const float* lin2_b  = (const float*)d_in[19];
    const float* bn7_g   = (const float*)d_in[20];
    const float* bn7_b   = (const float*)d_in[21];
    const float* lin3_w  = (const float*)d_in[22];
    const float* lin3_b  = (const float*)d_in[23];
    float* out = (float*)d_out;

    float *inner, *xxp, *Ap, *Bp, *X1, *X2, *X3, *X4, *Xc, *wd, *wcd, *gp;
    int* idxp;
    cudaGetSymbolAddress((void**)&inner, g_inner);
    cudaGetSymbolAddress((void**)&xxp,   g_xx);
    cudaGetSymbolAddress((void**)&idxp,  g_idx);
    cudaGetSymbolAddress((void**)&Ap,    g_A);
    cudaGetSymbolAddress((void**)&Bp,    g_Bc);
    cudaGetSymbolAddress((void**)&X1,    g_X1);
    cudaGetSymbolAddress((void**)&X2,    g_X2);
    cudaGetSymbolAddress((void**)&X3,    g_X3);
    cudaGetSymbolAddress((void**)&X4,    g_X4);
    cudaGetSymbolAddress((void**)&Xc,    g_Xc);
    cudaGetSymbolAddress((void**)&wd,    g_wd);
    cudaGetSymbolAddress((void**)&wcd,   g_wcd);
    cudaGetSymbolAddress((void**)&gp,    g_gpool);

    // edge conv stages
    run_edge_stage(x,  3,   64,  conv1_w, conv1_b, bn1_g, bn1_b, X1,
                   inner, xxp, idxp, wd, wcd, Ap, Bp);
    run_edge_stage(X1, 64,  64,  conv2_w, nullptr, bn2_g, bn2_b, X2,
                   inner, xxp, idxp, wd, wcd, Ap, Bp);
    run_edge_stage(X2, 64,  128, conv3_w, nullptr, bn3_g, bn3_b, X3,
                   inner, xxp, idxp, wd, wcd, Ap, Bp);
    run_edge_stage(X3, 128, 256, conv4_w, nullptr, bn4_g, bn4_b, X4,
                   inner, xxp, idxp, wd, wcd, Ap, Bp);

    // concat + conv5 + global max pool
    concat_kernel<<<dim3(NN, BB), 256>>>(X1, X2, X3, X4, Xc);
    dim3 g5(NN / TBM, NN / TBN, BB);
    gemm_nt<<<g5, 256>>>(Xc, conv5_w, inner, NN, NN, 512,
                         (long)NN * 512, 0, (long)NN * NN);
    maxcol_kernel<<<dim3(NN / 256, BB), 256>>>(inner, gp);

    // MLP head
    mlp_head_kernel<<<BB, 512>>>(gp, lin1_w, bn6_g, bn6_b,
                                 lin2_w, lin2_b, bn7_g, bn7_b,
                                 lin3_w, lin3_b, out);
}

// round 2
// speedup vs baseline: 1.7536x; 1.7536x over previous
#include <cuda_runtime.h>
#include <cuda_bf16.h>
#include <math.h>

// ---------------------------------------------------------------------------
// DGCNN forward.  B=8, N=1024, KNN=20.
// Features stored n-major. Stage outputs written directly into concat buffer
// Xc[b][n][512] at column offsets {0,64,128,256}.
// edge_conv factorization:  y[o,n,k] = (wd@x)[o,idx[n,k]] + ((wc-wd)@x)[o,n]
// ---------------------------------------------------------------------------

#define BB   8
#define NN   1024
#define KNN  20

// ------------------------- scratch (device globals) ------------------------
__device__ float g_inner[BB * NN * NN];     // 32MB: Gram matrices / conv5 out
__device__ float g_xx[BB * NN];
__device__ int   g_idx[BB * NN * KNN];
__device__ float g_AB[BB * NN * 512];       // [wd;wcd] @ x  (n-major, 2*O cols)
__device__ float g_Xc[BB * NN * 512];       // concat buffer (stage outputs)
__device__ float g_wbuf[96000];             // stacked [wd;wcd] for all stages
__device__ float g_gpool[BB * NN];

// stacked-weight offsets (floats)
#define W1_OFF 0        // 128*3   = 384
#define W2_OFF 384      // 128*64  = 8192
#define W3_OFF 8576     // 256*64  = 16384
#define W4_OFF 24960    // 512*128 = 65536
#define W_TOTAL 90496

// --------------------------- weight split (all stages) -----------------------
// out region layout per stage: rows 0..O-1 = w[:, :C], rows O..2O-1 = w[:,C:]-w[:,:C]
__device__ __forceinline__ void wsplit_one(const float* w, float* out,
                                           int O, int C, int i)
{
    int r = i / C, c = i % C;
    if (r < O) out[i] = w[(long)r * 2 * C + c];
    else {
        int o = r - O;
        out[i] = w[(long)o * 2 * C + C + c] - w[(long)o * 2 * C + c];
    }
}

__global__ void wsplit_all_kernel(const float* __restrict__ w1, const float* __restrict__ w2,
                                  const float* __restrict__ w3, const float* __restrict__ w4,
                                  float* __restrict__ out)
{
    int i = blockIdx.x * 256 + threadIdx.x;
    if (i >= W_TOTAL) return;
    if (i < W2_OFF)      wsplit_one(w1, out + W1_OFF, 64,  3,   i - W1_OFF);
    else if (i < W3_OFF) wsplit_one(w2, out + W2_OFF, 64,  64,  i - W2_OFF);
    else if (i < W4_OFF) wsplit_one(w3, out + W3_OFF, 128, 64,  i - W3_OFF);
    else                 wsplit_one(w4, out + W4_OFF, 256, 128, i - W4_OFF);
}

// --------------------------- row squared norms ------------------------------
__global__ void rownorm_kernel(const float* __restrict__ X, float* __restrict__ xx,
                               int C, int ldx)
{
    int i = blockIdx.x * blockDim.x + threadIdx.x;   // over B*N
    if (i < BB * NN) {
        const float* r = X + (long)i * ldx;
        float s = 0.f;
        for (int c = 0; c < C; c++) s += r[c] * r[c];
        xx[i] = s;
    }
}

// --------------------------- tiled GEMM (NT) --------------------------------
// C[m][n] = sum_k A[m][k] * B[n][k]
// BM=128, BN=64, BK=16, 256 threads, 8x4 register tile, float4 smem loads.
#define BM 128
#define BN 64
#define BK 16
#define PAD 4

__global__ __launch_bounds__(256) void gemm_nt(
        const float* __restrict__ A, const float* __restrict__ B,
        float* __restrict__ C, int M, int N, int K,
        int lda, int ldb, int ldc,
        long sA, long sB, long sC)
{
    int bz = blockIdx.z;
    A += (long)bz * sA;
    B += (long)bz * sB;
    C += (long)bz * sC;

    int m0 = blockIdx.x * BM;
    int n0 = blockIdx.y * BN;

    __shared__ float As[BK][BM + PAD];
    __shared__ float Bs[BK][BN + PAD];

    int tid = threadIdx.x;
    int ty = tid >> 4;          // 0..15  -> 8 rows each
    int tx = tid & 15;          // 0..15  -> 4 cols each

    float acc[8][4];
#pragma unroll
    for (int i = 0; i < 8; i++)
#pragma unroll
        for (int j = 0; j < 4; j++) acc[i][j] = 0.f;

    for (int k0 = 0; k0 < K; k0 += BK) {
        // load A tile: BM*BK = 2048 elems, 8 per thread
#pragma unroll
        for (int l0 = 0; l0 < (BM * BK) / 256; l0++) {
            int l = tid + l0 * 256;
            int r = l >> 4, c = l & 15;
            int ki = k0 + c;
            As[c][r] = (ki < K) ? A[(long)(m0 + r) * lda + ki] : 0.f;
        }
        // load B tile: BN*BK = 1024 elems, 4 per thread
#pragma unroll
        for (int l0 = 0; l0 < (BN * BK) / 256; l0++) {
            int l = tid + l0 * 256;
            int r = l >> 4, c = l & 15;
            int ki = k0 + c;
            Bs[c][r] = (ki < K) ? B[(long)(n0 + r) * ldb + ki] : 0.f;
        }
        __syncthreads();

#pragma unroll
        for (int kk = 0; kk < BK; kk++) {
            float4 a0 = *(const float4*)&As[kk][ty * 8];
            float4 a1 = *(const float4*)&As[kk][ty * 8 + 4];
            float4 bv = *(const float4*)&Bs[kk][tx * 4];
            float av[8] = {a0.x, a0.y, a0.z, a0.w, a1.x, a1.y, a1.z, a1.w};
            float bw[4] = {bv.x, bv.y, bv.z, bv.w};
#pragma unroll
            for (int i = 0; i < 8; i++)
#pragma unroll
                for (int j = 0; j < 4; j++) acc[i][j] += av[i] * bw[j];
        }
        __syncthreads();
    }

#pragma unroll
    for (int i = 0; i < 8; i++) {
        long mi = m0 + ty * 8 + i;
        float4 v = make_float4(acc[i][0], acc[i][1], acc[i][2], acc[i][3]);
        *(float4*)&C[mi * ldc + n0 + tx * 4] = v;
    }
}

// --------------------------- top-k (k=20), warp per row ----------------------
// dist[m] = 2*inner[n][m] - xx[n] - xx[m]; iterative argmax, tie -> lower idx
__global__ void topk_kernel(const float* __restrict__ inner,
                            const float* __restrict__ xx,
                            int* __restrict__ idx)
{
    int warp = threadIdx.x >> 5, lane = threadIdx.x & 31;
    int n = blockIdx.x * 8 + warp;
    int b = blockIdx.y;

    const float* row = inner + ((long)b * NN + n) * NN;
    float xn = xx[b * NN + n];

    float d[32];
#pragma unroll
    for (int j = 0; j < 32; j++) {
        int m = j * 32 + lane;
        d[j] = 2.f * row[m] - xn - xx[b * NN + m];
    }

    int* orow = idx + ((long)b * NN + n) * KNN;
    for (int it = 0; it < KNN; it++) {
        // local argmax over 32 regs (ascending j keeps smallest m on ties)
        float bv = d[0]; int bj = 0;
#pragma unroll
        for (int j = 1; j < 32; j++)
            if (d[j] > bv) { bv = d[j]; bj = j; }
        int bm = bj * 32 + lane;
        // warp reduce: larger value wins; tie -> smaller index
#pragma unroll
        for (int off = 16; off; off >>= 1) {
            float ov = __shfl_xor_sync(0xffffffffu, bv, off);
            int   om = __shfl_xor_sync(0xffffffffu, bm, off);
            if (ov > bv || (ov == bv && om < bm)) { bv = ov; bm = om; }
        }
        if (lane == 0) orow[it] = bm;
        if ((bm & 31) == lane) {
            int wj = bm >> 5;
#pragma unroll
            for (int j = 0; j < 32; j++)
                if (j == wj) d[j] = -INFINITY;
        }
    }
}

// --------------------------- gather + bn + lrelu + max ------------------------
// AB rows: [A(0..O-1) | Bc(O..2O-1)], row stride 2*O.  Output into Xc slice.
__global__ void gathermax_kernel(const float* __restrict__ AB,
                                 const int* __restrict__ idx,
                                 const float* __restrict__ bias,
                                 const float* __restrict__ gg,
                                 const float* __restrict__ bb,
                                 float* __restrict__ Xout, int O)
{
    int n = blockIdx.x, b = blockIdx.y;
    __shared__ int nb[KNN];
    if (threadIdx.x < KNN)
        nb[threadIdx.x] = idx[((long)b * NN + n) * KNN + threadIdx.x];
    __syncthreads();

    const float rs = rsqrtf(1.f + 1e-5f);
    int twoO = 2 * O;
    long rowbase = ((long)b * NN + n) * twoO;
    for (int o = threadIdx.x; o < O; o += blockDim.x) {
        float base = AB[rowbase + O + o] + (bias ? bias[o] : 0.f);
        float gs = gg[o] * rs;
        float bo = bb[o];
        float acc = -INFINITY;
#pragma unroll
        for (int k = 0; k < KNN; k++) {
            float a = AB[((long)b * NN + nb[k]) * twoO + o];
            float v = (a + base) * gs + bo;
            v = (v >= 0.f) ? v : 0.01f * v;
            acc = fmaxf(acc, v);
        }
        Xout[((long)b * NN + n) * 512 + o] = acc;
    }
}

// --------------------------- column max over n --------------------------------
__global__ void maxcol_kernel(const float* __restrict__ e, float* __restrict__ gpool)
{
    int b = blockIdx.y;
    int o = blockIdx.x * 256 + threadIdx.x;
    float m = -INFINITY;
    const float* eb = e + (long)b * NN * NN;
    for (int n = 0; n < NN; n++)
        m = fmaxf(m, eb[(long)n * NN + o]);
    gpool[b * NN + o] = m;
}

// --------------------------- MLP head -----------------------------------------
__global__ void mlp_head_kernel(const float* __restrict__ gpool,
                                const float* __restrict__ w1,
                                const float* __restrict__ g6, const float* __restrict__ b6,
                                const float* __restrict__ w2, const float* __restrict__ b2v,
                                const float* __restrict__ g7, const float* __restrict__ b7,
                                const float* __restrict__ w3, const float* __restrict__ b3v,
                                float* __restrict__ out)
{
    int b = blockIdx.x;
    int t = threadIdx.x;    // 512 threads
    __shared__ float s0[1024];
    __shared__ float s1[512];
    __shared__ float s2[256];

    for (int i = t; i < 1024; i += 512) s0[i] = gpool[b * 1024 + i];
    __syncthreads();

    const float rs = rsqrtf(1.f + 1e-5f);
    {
        const float* wr = w1 + (long)t * 1024;
        float acc = 0.f;
        for (int k = 0; k < 1024; k++) acc += s0[k] * wr[k];
        acc = acc * (g6[t] * rs) + b6[t];
        s1[t] = (acc >= 0.f) ? acc : 0.01f * acc;
    }
    __syncthreads();

    if (t < 256) {
        const float* wr = w2 + (long)t * 512;
        float acc = 0.f;
        for (int k = 0; k < 512; k++) acc += s1[k] * wr[k];
        acc += b2v[t];
        acc = acc * (g7[t] * rs) + b7[t];
        s2[t] = (acc >= 0.f) ? acc : 0.01f * acc;
    }
    __syncthreads();

    if (t < 40) {
        const float* wr = w3 + (long)t * 256;
        float acc = 0.f;
        for (int k = 0; k < 256; k++) acc += s2[k] * wr[k];
        out[b * 40 + t] = acc + b3v[t];
    }
}

// ---------------------------------------------------------------------------
// host side
// ---------------------------------------------------------------------------
static void run_edge_stage(const float* X, int ldx, long strideX, int C, int O,
                           const float* wcomb,      // stacked [wd;wcd], 2O x C
                           const float* bias,
                           const float* gg, const float* bbv,
                           float* Xout,             // Xc slice base (ld 512)
                           float* inner, float* xxp, int* idxp, float* ABp)
{
    rownorm_kernel<<<(BB * NN + 255) / 256, 256>>>(X, xxp, C, ldx);

    // Gram: inner[b] = X X^T  (1024x1024, K=C)
    dim3 gi(NN / BM, NN / BN, BB);
    gemm_nt<<<gi, 256>>>(X, X, inner, NN, NN, C, ldx, ldx, NN,
                         strideX, strideX, (long)NN * NN);

    topk_kernel<<<dim3(NN / 8, BB), 256>>>(inner, xxp, idxp);

    // features: AB[b] = X @ [wd;wcd]^T   (1024 x 2O)
    int twoO = 2 * O;
    dim3 ga(NN / BM, twoO / BN, BB);
    gemm_nt<<<ga, 256>>>(X, wcomb, ABp, NN, twoO, C, ldx, C, twoO,
                         strideX, 0, (long)NN * twoO);

    gathermax_kernel<<<dim3(NN, BB), 256>>>(ABp, idxp, bias, gg, bbv, Xout, O);
}

extern "C" void kernel_launch(void* const* d_in, const int* in_sizes, int n_in,
                              void* d_out, int out_size)
{
    const float* x       = (const float*)d_in[0];    // (8,1024,3)
    const float* conv1_w = (const float*)d_in[1];
    const float* conv1_b = (const float*)d_in[2];
    const float* bn1_g   = (const float*)d_in[3];
    const float* bn1_b   = (const float*)d_in[4];
    const float* conv2_w = (const float*)d_in[5];
    const float* bn2_g   = (const float*)d_in[6];
    const float* bn2_b   = (const float*)d_in[7];
    const float* conv3_w = (const float*)d_in[8];
    const float* bn3_g   = (const float*)d_in[9];
    const float* bn3_b   = (const float*)d_in[10];
    const float* conv4_w = (const float*)d_in[11];
    const float* bn4_g   = (const float*)d_in[12];
    const float* bn4_b   = (const float*)d_in[13];
    const float* conv5_w = (const float*)d_in[14];
    const float* lin1_w  = (const float*)d_in[15];
    const float* bn6_g   = (const float*)d_in[16];
    const float* bn6_b   = (const float*)d_in[17];
    const float* lin2_w  = (const float*)d_in[18];
    const float* lin2_b  = (const float*)d_in[19];
    const float* bn7_g   = (const float*)d_in[20];
    const float* bn7_b   = (const float*)d_in[21];
    const float* lin3_w  = (const float*)d_in[22];
    const float* lin3_b  = (const float*)d_in[23];
    float* out = (float*)d_out;

    float *inner, *xxp, *ABp, *Xc, *wbuf, *gp;
    int* idxp;
    cudaGetSymbolAddress((void**)&inner, g_inner);
    cudaGetSymbolAddress((void**)&xxp,   g_xx);
    cudaGetSymbolAddress((void**)&idxp,  g_idx);
    cudaGetSymbolAddress((void**)&ABp,   g_AB);
    cudaGetSymbolAddress((void**)&Xc,    g_Xc);
    cudaGetSymbolAddress((void**)&wbuf,  g_wbuf);
    cudaGetSymbolAddress((void**)&gp,    g_gpool);

    wsplit_all_kernel<<<(W_TOTAL + 255) / 256, 256>>>(conv1_w, conv2_w, conv3_w, conv4_w, wbuf);

    // edge conv stages (outputs go straight into concat slices of Xc)
    run_edge_stage(x,        3,   (long)NN * 3,   3,   64,  wbuf + W1_OFF, conv1_b,
                   bn1_g, bn1_b, Xc + 0,   inner, xxp, idxp, ABp);
    run_edge_stage(Xc + 0,   512, (long)NN * 512, 64,  64,  wbuf + W2_OFF, nullptr,
                   bn2_g, bn2_b, Xc + 64,  inner, xxp, idxp, ABp);
    run_edge_stage(Xc + 64,  512, (long)NN * 512, 64,  128, wbuf + W3_OFF, nullptr,
                   bn3_g, bn3_b, Xc + 128, inner, xxp, idxp, ABp);
    run_edge_stage(Xc + 128, 512, (long)NN * 512, 128, 256, wbuf + W4_OFF, nullptr,
                   bn4_g, bn4_b, Xc + 256, inner, xxp, idxp, ABp);

    // conv5:  e[b] = Xc @ conv5_w^T  (1024 x 1024, K=512), then max over n
    dim3 g5(NN / BM, NN / BN, BB);
    gemm_nt<<<g5, 256>>>(Xc, conv5_w, inner, NN, NN, 512, 512, 512, NN,
                         (long)NN * 512, 0, (long)NN * NN);
    maxcol_kernel<<<dim3(NN / 256, BB), 256>>>(inner, gp);

    // MLP head
    mlp_head_kernel<<<BB, 512>>>(gp, lin1_w, bn6_g, bn6_b,
                                 lin2_w, lin2_b, bn7_g, bn7_b,
                                 lin3_w, lin3_b, out);
}